// round 6
// baseline (speedup 1.0000x reference)
#include <cuda_runtime.h>
#include <math.h>

#define BATCH 8
#define NPTS  2048
#define NJ    21
#define NWGT  778
#define TOTAL (BATCH*NPTS)

// ---------------- device scratch ----------------
__device__ unsigned int g_wbits[NWGT];
__device__ float4 g_q4[TOTAL];          // gen: x,y,z,|q|^2
__device__ unsigned int g_qbits[TOTAL]; // gen joint-mask bits
__device__ int    g_label[TOTAL];       // argmin segment label per (b,m)
__device__ float4 g_tsorted[TOTAL];     // target sorted by label: x,y,z,|t|^2
__device__ int    g_offs[BATCH*(NJ+1)];
__device__ float  g_cham1, g_cham2;
__device__ float  g_j1[NJ], g_j2[NJ];

__constant__ float c_ranges[NJ*6] = {
  -1.57f,1.57f, -1.57f,1.57f, -1.57f,1.57f,
  -1.05f,1.05f, 0.f,0.f, -0.79f,0.26f,
  -0.52f,0.52f, 0.f,0.f, -0.35f,0.79f,
  -0.26f,0.26f, 0.f,0.f, 0.f,0.f,
  -1.05f,0.f,   0.f,0.f, 0.f,0.f,
   0.f,0.f,     0.f,0.f, 0.f,0.f,
  -1.05f,0.26f, 0.f,0.f, -0.52f,0.26f,
  -0.52f,0.f,   0.f,0.f, 0.f,0.f,
  -0.52f,0.f,   0.f,0.f, 0.f,0.f,
   0.f,0.f,     0.f,0.f, 0.f,0.f,
  -1.05f,0.26f, 0.f,0.f, -0.52f,0.26f,
  -0.52f,0.f,   0.f,0.f, 0.f,0.f,
  -0.52f,0.f,   0.f,0.f, 0.f,0.f,
   0.f,0.f,     0.f,0.f, 0.f,0.f,
  -1.05f,0.26f, 0.f,0.f, -0.52f,0.26f,
  -0.52f,0.f,   0.f,0.f, 0.f,0.f,
  -0.52f,0.f,   0.f,0.f, 0.f,0.f,
   0.f,0.f,     0.f,0.f, 0.f,0.f,
  -1.05f,0.26f, 0.f,0.f, -0.52f,0.26f,
  -0.52f,0.f,   0.f,0.f, 0.f,0.f,
  -0.52f,0.f,   0.f,0.f, 0.f,0.f
};

// ---- K1: wbits + zero accumulators ----
__global__ void k_prep(const float* __restrict__ bw) {
    int t = threadIdx.x;
    if (t < NJ) { g_j1[t] = 0.f; g_j2[t] = 0.f; }
    if (t == 0) { g_cham1 = 0.f; g_cham2 = 0.f; }
    if (t < NWGT) {
        unsigned int bits = 0;
#pragma unroll
        for (int i = 0; i < NJ; i++)
            bits |= (bw[i*NWGT + t] > 0.15f) ? (1u << i) : 0u;
        g_wbits[t] = bits;
    }
}

// ---- K2: pack gen (norm + bits) + labels (coalesced via smem stage) ----
__global__ void __launch_bounds__(256) k_pack_label(
        const float* __restrict__ gen, const int* __restrict__ idxs,
        const float* __restrict__ seg) {
    __shared__ float sl[256*NJ];
    int t = threadIdx.x, blk = blockIdx.x;
    int gid = blk*256 + t;
    const float* segb = seg + (size_t)blk*256*NJ;
    for (int i = t; i < 256*NJ; i += 256) sl[i] = segb[i];
    float x = gen[3*gid], y = gen[3*gid+1], z = gen[3*gid+2];
    float4 q; q.x = x; q.y = y; q.z = z; q.w = x*x + y*y + z*z;
    g_q4[gid] = q;
    g_qbits[gid] = g_wbits[idxs[gid]];
    __syncthreads();
    const float* s = &sl[t*NJ];
    float best = s[0]; int bi = 0;
#pragma unroll
    for (int k = 1; k < NJ; k++) {
        float v = s[k];
        if (v < best) { best = v; bi = k; }
    }
    g_label[gid] = bi;
}

// ---- K3: per-batch counting sort (hist + prefix + scatter), 8 blocks ----
__global__ void __launch_bounds__(512) k_sort(const float* __restrict__ tpc) {
    __shared__ int hist[NJ];
    __shared__ int cur[NJ];
    __shared__ int labs[NPTS];
    int t = threadIdx.x, b = blockIdx.x;
    if (t < NJ) hist[t] = 0;
    __syncthreads();
    int base = b << 11;
#pragma unroll
    for (int k = 0; k < 4; k++) {
        int i = t + 512*k;
        int lab = g_label[base + i];
        labs[i] = lab;
        atomicAdd(&hist[lab], 1);
    }
    __syncthreads();
    if (t == 0) {
        int run = 0;
        for (int j = 0; j < NJ; j++) {
            g_offs[b*(NJ+1) + j] = run;
            cur[j] = run;
            run += hist[j];
        }
        g_offs[b*(NJ+1) + NJ] = run;
    }
    __syncthreads();
#pragma unroll
    for (int k = 0; k < 4; k++) {
        int i = t + 512*k;
        int lab = labs[i];
        int pos = atomicAdd(&cur[lab], 1);
        int gi = base + i;
        float x = tpc[3*gi], y = tpc[3*gi+1], z = tpc[3*gi+2];
        float4 v; v.x = x; v.y = y; v.z = z; v.w = x*x + y*y + z*z;
        g_tsorted[base + pos] = v;
    }
}

// ---- K4: row pass. 8 queries/warp, quarter-warps split each group's range. ----
__global__ void __launch_bounds__(128) k_row() {
    __shared__ float4 sT[NPTS];      // 32 KB
    __shared__ int    soff[NJ+1];
    __shared__ float  sj[NJ];
    __shared__ float  scham;
    int t = threadIdx.x;
    int b = blockIdx.x >> 6;         // 64 blocks per batch
    int qblk = blockIdx.x & 63;

    for (int i = t; i < NPTS; i += 128) sT[i] = g_tsorted[(b << 11) + i];
    if (t < NJ+1) soff[t] = g_offs[b*(NJ+1) + t];
    if (t < NJ) sj[t] = 0.f;
    if (t == 0) scham = 0.f;
    __syncthreads();

    int warp = t >> 5, lane = t & 31;
    int quar = lane >> 3, ql = lane & 7;
    int qi = qblk*32 + warp*8 + ql;
    float4 q = g_q4[(b << 11) + qi];
    unsigned int bits = g_qbits[(b << 11) + qi];
    float qn2 = q.w;
    float gmall = 1e30f;

    for (int grp = 0; grp < NJ; grp++) {
        int s = soff[grp], e = soff[grp+1];
        int len = e - s;
        if (len > 0) {
            int hlen = (len + 3) >> 2;
            int m0 = s + quar*hlen;
            float gm = 1e30f;
#pragma unroll 4
            for (int i = 0; i < hlen; i++) {
                int m = m0 + i;
                m = (m < e) ? m : (e - 1);     // duplicate tail: harmless for min
                float4 tp = sT[m];
                float dot = q.x*tp.x;
                dot = fmaf(q.y, tp.y, dot);
                dot = fmaf(q.z, tp.z, dot);
                float val = fmaf(-2.f, dot, tp.w);   // |t|^2 - 2 q.t
                gm = fminf(gm, val);
            }
            gm = fminf(gm, __shfl_xor_sync(0xffffffffu, gm, 8));
            gm = fminf(gm, __shfl_xor_sync(0xffffffffu, gm, 16));
            gmall = fminf(gmall, gm);
            if (quar == 0 && ((bits >> grp) & 1u)) {
                float d = sqrtf(fmaxf(gm + qn2, 0.f));
                if (d < 10.f) atomicAdd(&sj[grp], d);
            }
        }
    }
    if (quar == 0) {
        float d1 = sqrtf(fmaxf(gmall + qn2, 0.f));
        atomicAdd(&scham, d1);
    }
    __syncthreads();
    if (t < NJ) atomicAdd(&g_j1[t], sj[t]);
    if (t == 0) atomicAdd(&g_cham1, scham);
}

// ---- K5: column pass. 8 targets/warp, quarter-warps split the gen scan. ----
__global__ void __launch_bounds__(128) k_col(const float* __restrict__ tpc) {
    __shared__ float4 sQ[NPTS];              // 32 KB
    __shared__ unsigned int sB[NPTS];        // 8 KB
    __shared__ float sj[NJ];
    __shared__ float scham;
    int t = threadIdx.x;
    int b = blockIdx.x >> 6;
    int mblk = blockIdx.x & 63;

    for (int i = t; i < NPTS; i += 128) {
        sQ[i] = g_q4[(b << 11) + i];
        sB[i] = g_qbits[(b << 11) + i];
    }
    if (t < NJ) sj[t] = 0.f;
    if (t == 0) scham = 0.f;
    __syncthreads();

    int warp = t >> 5, lane = t & 31;
    int quar = lane >> 3, ql = lane & 7;
    int mi = mblk*32 + warp*8 + ql;
    int gi = (b << 11) + mi;
    float tx = tpc[3*gi], ty = tpc[3*gi+1], tz = tpc[3*gi+2];
    float tn2 = tx*tx + ty*ty + tz*tz;
    int p = g_label[gi];
    unsigned int mymask = 1u << p;
    float gmin = 1e30f, pmin = 1e30f;
    int n0 = quar * (NPTS/4);
    const uint4* sB4 = (const uint4*)sB;

#pragma unroll 2
    for (int i = 0; i < NPTS/4; i += 4) {
        uint4 bb = sB4[(n0 + i) >> 2];
        unsigned int bbv[4] = {bb.x, bb.y, bb.z, bb.w};
#pragma unroll
        for (int j = 0; j < 4; j++) {
            float4 qn = sQ[n0 + i + j];
            float dot = tx*qn.x;
            dot = fmaf(ty, qn.y, dot);
            dot = fmaf(tz, qn.z, dot);
            float val = fmaf(-2.f, dot, qn.w);   // |q|^2 - 2 t.q
            gmin = fminf(gmin, val);
            if (bbv[j] & mymask) pmin = fminf(pmin, val);
        }
    }
    gmin = fminf(gmin, __shfl_xor_sync(0xffffffffu, gmin, 8));
    gmin = fminf(gmin, __shfl_xor_sync(0xffffffffu, gmin, 16));
    pmin = fminf(pmin, __shfl_xor_sync(0xffffffffu, pmin, 8));
    pmin = fminf(pmin, __shfl_xor_sync(0xffffffffu, pmin, 16));
    if (quar == 0) {
        float d  = sqrtf(fmaxf(gmin + tn2, 0.f));
        float dj = sqrtf(fmaxf(pmin + tn2, 0.f));
        atomicAdd(&scham, d);
        if (dj < 10.f) atomicAdd(&sj[p], dj);
    }
    __syncthreads();
    if (t < NJ) atomicAdd(&g_j2[t], sj[t]);
    if (t == 0) atomicAdd(&g_cham2, scham);
}

// ---- K6: finalize ----
__global__ void k_final(const float* __restrict__ cp, const float* __restrict__ qt,
                        const float* __restrict__ tc, float* __restrict__ out) {
    __shared__ float s_coord, s_p;
    int t = threadIdx.x;
    if (t == 0) { s_coord = 0.f; s_p = 0.f; }
    __syncthreads();

    float ca = 0.f;
    for (int i = t; i < BATCH*NJ*3; i += blockDim.x) {
        float d = cp[i] - tc[i];
        ca += d * d;
    }
    float pa = 0.f;
    for (int i = t; i < BATCH*NJ; i += blockDim.x) {
        int j = i % NJ;
        float w = qt[4*i], x = qt[4*i+1], y = qt[4*i+2], z = qt[4*i+3];
        float inv = 1.0f / sqrtf(w*w + x*x + y*y + z*z);
        w *= inv; x *= inv; y *= inv; z *= inv;
        float a0 = atan2f(2.f*(w*x + y*z), 1.f - 2.f*(x*x + y*y));
        float a1 = asinf(fminf(fmaxf(2.f*(w*y - z*x), -1.f), 1.f));
        float a2 = atan2f(2.f*(w*z + x*y), 1.f - 2.f*(y*y + z*z));
        float a[3] = {a0, a1, a2};
#pragma unroll
        for (int c = 0; c < 3; c++) {
            float lo = c_ranges[j*6 + c*2], hi = c_ranges[j*6 + c*2 + 1];
            pa += fmaxf(lo - a[c], 0.f) + fmaxf(a[c] - hi, 0.f);
        }
    }
    atomicAdd(&s_coord, ca);
    atomicAdd(&s_p, pa);
    __syncthreads();
    if (t == 0) {
        float coord = s_coord / (float)(BATCH*NJ*3);
        float pl    = s_p / (float)(BATCH*NJ);
        float cham  = (g_cham1 + g_cham2) / (float)TOTAL;
        float jm = 0.f;
        for (int i = 0; i < NJ; i++) {
            float jl = (g_j1[i] + g_j2[i]) / (float)TOTAL;
            out[2 + i] = jl;
            jm += jl;
        }
        jm /= (float)NJ;
        out[0]  = 0.1f*cham + 0.1f*jm + coord + 0.1f*pl;
        out[1]  = coord;
        out[23] = cham;
        out[24] = pl;
    }
}

// ---------------- launch ----------------
extern "C" void kernel_launch(void* const* d_in, const int* in_sizes, int n_in,
                              void* d_out, int out_size) {
    const float* gen_pc      = (const float*)d_in[0];
    const int*   out_idxs    = (const int*)  d_in[1];
    const float* coords_pred = (const float*)d_in[2];
    const float* quats       = (const float*)d_in[3];
    const float* seg_logits  = (const float*)d_in[4];
    const float* bone_w      = (const float*)d_in[5];
    const float* tcoords     = (const float*)d_in[6];
    const float* target_pc   = (const float*)d_in[7];
    float* out = (float*)d_out;

    k_prep       <<<1, 1024>>>(bone_w);
    k_pack_label <<<TOTAL/256, 256>>>(gen_pc, out_idxs, seg_logits);
    k_sort       <<<BATCH, 512>>>(target_pc);
    k_row        <<<512, 128>>>();
    k_col        <<<512, 128>>>(target_pc);
    k_final      <<<1, 256>>>(coords_pred, quats, tcoords, out);
}

// round 9
// speedup vs baseline: 1.1298x; 1.1298x over previous
#include <cuda_runtime.h>
#include <math.h>

#define BATCH 8
#define NPTS  2048
#define NJ    21
#define NWGT  778
#define TOTAL (BATCH*NPTS)

// ---------------- device scratch ----------------
__device__ unsigned int g_wbits[NWGT];
__device__ float4 g_q4[TOTAL];          // gen: x,y,z,|q|^2
__device__ unsigned int g_qbits[TOTAL]; // gen joint-mask bits
__device__ int    g_label[TOTAL];       // argmin segment label per (b,m)
__device__ float4 g_tsorted[TOTAL];     // target sorted by label: x,y,z,|t|^2
__device__ int    g_offs[BATCH*(NJ+1)];
__device__ float  g_cham1, g_cham2;
__device__ float  g_j1[NJ], g_j2[NJ];

__constant__ float c_ranges[NJ*6] = {
  -1.57f,1.57f, -1.57f,1.57f, -1.57f,1.57f,
  -1.05f,1.05f, 0.f,0.f, -0.79f,0.26f,
  -0.52f,0.52f, 0.f,0.f, -0.35f,0.79f,
  -0.26f,0.26f, 0.f,0.f, 0.f,0.f,
  -1.05f,0.f,   0.f,0.f, 0.f,0.f,
   0.f,0.f,     0.f,0.f, 0.f,0.f,
  -1.05f,0.26f, 0.f,0.f, -0.52f,0.26f,
  -0.52f,0.f,   0.f,0.f, 0.f,0.f,
  -0.52f,0.f,   0.f,0.f, 0.f,0.f,
   0.f,0.f,     0.f,0.f, 0.f,0.f,
  -1.05f,0.26f, 0.f,0.f, -0.52f,0.26f,
  -0.52f,0.f,   0.f,0.f, 0.f,0.f,
  -0.52f,0.f,   0.f,0.f, 0.f,0.f,
   0.f,0.f,     0.f,0.f, 0.f,0.f,
  -1.05f,0.26f, 0.f,0.f, -0.52f,0.26f,
  -0.52f,0.f,   0.f,0.f, 0.f,0.f,
  -0.52f,0.f,   0.f,0.f, 0.f,0.f,
   0.f,0.f,     0.f,0.f, 0.f,0.f,
  -1.05f,0.26f, 0.f,0.f, -0.52f,0.26f,
  -0.52f,0.f,   0.f,0.f, 0.f,0.f,
  -0.52f,0.f,   0.f,0.f, 0.f,0.f
};

// ---- K1: wbits + zero accumulators ----
__global__ void k_prep(const float* __restrict__ bw) {
    int t = threadIdx.x;
    if (t < NJ) { g_j1[t] = 0.f; g_j2[t] = 0.f; }
    if (t == 0) { g_cham1 = 0.f; g_cham2 = 0.f; }
    if (t < NWGT) {
        unsigned int bits = 0;
#pragma unroll
        for (int i = 0; i < NJ; i++)
            bits |= (bw[i*NWGT + t] > 0.15f) ? (1u << i) : 0u;
        g_wbits[t] = bits;
    }
}

// ---- K2: pack gen (norm + bits) + labels (coalesced via smem stage) ----
__global__ void __launch_bounds__(256) k_pack_label(
        const float* __restrict__ gen, const int* __restrict__ idxs,
        const float* __restrict__ seg) {
    __shared__ float sl[256*NJ];
    int t = threadIdx.x, blk = blockIdx.x;
    int gid = blk*256 + t;
    const float* segb = seg + (size_t)blk*256*NJ;
    for (int i = t; i < 256*NJ; i += 256) sl[i] = segb[i];
    float x = gen[3*gid], y = gen[3*gid+1], z = gen[3*gid+2];
    float4 q; q.x = x; q.y = y; q.z = z; q.w = x*x + y*y + z*z;
    g_q4[gid] = q;
    g_qbits[gid] = g_wbits[idxs[gid]];
    __syncthreads();
    const float* s = &sl[t*NJ];
    float best = s[0]; int bi = 0;
#pragma unroll
    for (int k = 1; k < NJ; k++) {
        float v = s[k];
        if (v < best) { best = v; bi = k; }
    }
    g_label[gid] = bi;
}

// ---- K3: per-batch counting sort (hist + prefix + scatter) ----
__global__ void __launch_bounds__(512) k_sort(const float* __restrict__ tpc) {
    __shared__ int hist[NJ];
    __shared__ int cur[NJ];
    __shared__ int labs[NPTS];
    int t = threadIdx.x, b = blockIdx.x;
    if (t < NJ) hist[t] = 0;
    __syncthreads();
    int base = b << 11;
#pragma unroll
    for (int k = 0; k < 4; k++) {
        int i = t + 512*k;
        int lab = g_label[base + i];
        labs[i] = lab;
        atomicAdd(&hist[lab], 1);
    }
    __syncthreads();
    if (t == 0) {
        int run = 0;
        for (int j = 0; j < NJ; j++) {
            g_offs[b*(NJ+1) + j] = run;
            cur[j] = run;
            run += hist[j];
        }
        g_offs[b*(NJ+1) + NJ] = run;
    }
    __syncthreads();
#pragma unroll
    for (int k = 0; k < 4; k++) {
        int i = t + 512*k;
        int lab = labs[i];
        int pos = atomicAdd(&cur[lab], 1);
        int gi = base + i;
        float x = tpc[3*gi], y = tpc[3*gi+1], z = tpc[3*gi+2];
        float4 v; v.x = x; v.y = y; v.z = z; v.w = x*x + y*y + z*z;
        g_tsorted[base + pos] = v;
    }
}

// ---- K4: FUSED main pass. Blocks 0-255: row; 256-511: col.
// Each warp: 16 queries/targets, 2 per lane (ql, ql+8), quarter-split ranges.
struct RowS { float4 sT[NPTS]; int soff[NJ+1]; float sj[NJ]; float scham; };
struct ColS { float4 sQ[NPTS]; unsigned int sB[NPTS]; float sj[NJ]; float scham; };
union MainS { RowS r; ColS c; };

__global__ void __launch_bounds__(128) k_main(const float* __restrict__ tpc) {
    __shared__ MainS sm;
    int t = threadIdx.x;
    int warp = t >> 5, lane = t & 31;
    int quar = lane >> 3, ql = lane & 7;

    if (blockIdx.x < 256) {
        // ================= ROW =================
        int b = blockIdx.x >> 5;            // 32 blocks per batch
        int qblk = blockIdx.x & 31;         // 64 queries per block
        for (int i = t; i < NPTS; i += 128) sm.r.sT[i] = g_tsorted[(b << 11) + i];
        if (t < NJ+1) sm.r.soff[t] = g_offs[b*(NJ+1) + t];
        if (t < NJ) sm.r.sj[t] = 0.f;
        if (t == 0) sm.r.scham = 0.f;
        __syncthreads();

        int qbase = (b << 11) + qblk*64 + warp*16;
        float4 qa = g_q4[qbase + ql];
        float4 qb = g_q4[qbase + 8 + ql];
        unsigned int bits_a = g_qbits[qbase + ql];
        unsigned int bits_b = g_qbits[qbase + 8 + ql];
        float gmall_a = 1e30f, gmall_b = 1e30f;

        for (int grp = 0; grp < NJ; grp++) {
            int s = sm.r.soff[grp], e = sm.r.soff[grp+1];
            int hlen = (e - s + 3) >> 2;
            int m0 = s + quar*hlen;
            int mend = min(m0 + hlen, e);
            float gma = 1e30f, gmb = 1e30f;
#pragma unroll 2
            for (int m = m0; m < mend; m++) {
                float4 tp = sm.r.sT[m];
                float da = qa.x*tp.x; da = fmaf(qa.y, tp.y, da); da = fmaf(qa.z, tp.z, da);
                float db = qb.x*tp.x; db = fmaf(qb.y, tp.y, db); db = fmaf(qb.z, tp.z, db);
                gma = fminf(gma, fmaf(-2.f, da, tp.w));
                gmb = fminf(gmb, fmaf(-2.f, db, tp.w));
            }
            gma = fminf(gma, __shfl_xor_sync(0xffffffffu, gma, 8));
            gma = fminf(gma, __shfl_xor_sync(0xffffffffu, gma, 16));
            gmb = fminf(gmb, __shfl_xor_sync(0xffffffffu, gmb, 8));
            gmb = fminf(gmb, __shfl_xor_sync(0xffffffffu, gmb, 16));
            gmall_a = fminf(gmall_a, gma);
            gmall_b = fminf(gmall_b, gmb);
            if (quar == 0 && ((bits_a >> grp) & 1u)) {
                float d = sqrtf(fmaxf(gma + qa.w, 0.f));
                if (d < 10.f) atomicAdd(&sm.r.sj[grp], d);
            }
            if (quar == 1 && ((bits_b >> grp) & 1u)) {
                float d = sqrtf(fmaxf(gmb + qb.w, 0.f));
                if (d < 10.f) atomicAdd(&sm.r.sj[grp], d);
            }
        }
        if (quar == 0) atomicAdd(&sm.r.scham, sqrtf(fmaxf(gmall_a + qa.w, 0.f)));
        if (quar == 1) atomicAdd(&sm.r.scham, sqrtf(fmaxf(gmall_b + qb.w, 0.f)));
        __syncthreads();
        if (t < NJ) atomicAdd(&g_j1[t], sm.r.sj[t]);
        if (t == 0) atomicAdd(&g_cham1, sm.r.scham);
    } else {
        // ================= COL =================
        int blk = blockIdx.x - 256;
        int b = blk >> 5;
        int mblk = blk & 31;
        for (int i = t; i < NPTS; i += 128) {
            sm.c.sQ[i] = g_q4[(b << 11) + i];
            sm.c.sB[i] = g_qbits[(b << 11) + i];
        }
        if (t < NJ) sm.c.sj[t] = 0.f;
        if (t == 0) sm.c.scham = 0.f;
        __syncthreads();

        int mbase = (b << 11) + mblk*64 + warp*16;
        int gia = mbase + ql, gib = mbase + 8 + ql;
        float tax = tpc[3*gia], tay = tpc[3*gia+1], taz = tpc[3*gia+2];
        float tbx = tpc[3*gib], tby = tpc[3*gib+1], tbz = tpc[3*gib+2];
        float tan2 = tax*tax + tay*tay + taz*taz;
        float tbn2 = tbx*tbx + tby*tby + tbz*tbz;
        int pa = g_label[gia], pb = g_label[gib];
        unsigned int maska = 1u << pa, maskb = 1u << pb;
        float gmina = 1e30f, gminb = 1e30f, pmina = 1e30f, pminb = 1e30f;
        int n0 = quar * (NPTS/4);

#pragma unroll 4
        for (int i = 0; i < NPTS/4; i++) {
            int n = n0 + i;
            float4 qn = sm.c.sQ[n];
            unsigned int bb = sm.c.sB[n];
            float da = tax*qn.x; da = fmaf(tay, qn.y, da); da = fmaf(taz, qn.z, da);
            float db = tbx*qn.x; db = fmaf(tby, qn.y, db); db = fmaf(tbz, qn.z, db);
            float va = fmaf(-2.f, da, qn.w);
            float vb = fmaf(-2.f, db, qn.w);
            gmina = fminf(gmina, va);
            gminb = fminf(gminb, vb);
            pmina = fminf(pmina, (bb & maska) ? va : 1e30f);
            pminb = fminf(pminb, (bb & maskb) ? vb : 1e30f);
        }
        gmina = fminf(gmina, __shfl_xor_sync(0xffffffffu, gmina, 8));
        gmina = fminf(gmina, __shfl_xor_sync(0xffffffffu, gmina, 16));
        gminb = fminf(gminb, __shfl_xor_sync(0xffffffffu, gminb, 8));
        gminb = fminf(gminb, __shfl_xor_sync(0xffffffffu, gminb, 16));
        pmina = fminf(pmina, __shfl_xor_sync(0xffffffffu, pmina, 8));
        pmina = fminf(pmina, __shfl_xor_sync(0xffffffffu, pmina, 16));
        pminb = fminf(pminb, __shfl_xor_sync(0xffffffffu, pminb, 8));
        pminb = fminf(pminb, __shfl_xor_sync(0xffffffffu, pminb, 16));
        if (quar == 0) {
            atomicAdd(&sm.c.scham, sqrtf(fmaxf(gmina + tan2, 0.f)));
            float dj = sqrtf(fmaxf(pmina + tan2, 0.f));
            if (dj < 10.f) atomicAdd(&sm.c.sj[pa], dj);
        }
        if (quar == 1) {
            atomicAdd(&sm.c.scham, sqrtf(fmaxf(gminb + tbn2, 0.f)));
            float dj = sqrtf(fmaxf(pminb + tbn2, 0.f));
            if (dj < 10.f) atomicAdd(&sm.c.sj[pb], dj);
        }
        __syncthreads();
        if (t < NJ) atomicAdd(&g_j2[t], sm.c.sj[t]);
        if (t == 0) atomicAdd(&g_cham2, sm.c.scham);
    }
}

// ---- K5: finalize ----
__global__ void k_final(const float* __restrict__ cp, const float* __restrict__ qt,
                        const float* __restrict__ tc, float* __restrict__ out) {
    __shared__ float s_coord, s_p;
    int t = threadIdx.x;
    if (t == 0) { s_coord = 0.f; s_p = 0.f; }
    __syncthreads();

    float ca = 0.f;
    for (int i = t; i < BATCH*NJ*3; i += blockDim.x) {
        float d = cp[i] - tc[i];
        ca += d * d;
    }
    float pa = 0.f;
    for (int i = t; i < BATCH*NJ; i += blockDim.x) {
        int j = i % NJ;
        float w = qt[4*i], x = qt[4*i+1], y = qt[4*i+2], z = qt[4*i+3];
        float inv = 1.0f / sqrtf(w*w + x*x + y*y + z*z);
        w *= inv; x *= inv; y *= inv; z *= inv;
        float a0 = atan2f(2.f*(w*x + y*z), 1.f - 2.f*(x*x + y*y));
        float a1 = asinf(fminf(fmaxf(2.f*(w*y - z*x), -1.f), 1.f));
        float a2 = atan2f(2.f*(w*z + x*y), 1.f - 2.f*(y*y + z*z));
        float a[3] = {a0, a1, a2};
#pragma unroll
        for (int c = 0; c < 3; c++) {
            float lo = c_ranges[j*6 + c*2], hi = c_ranges[j*6 + c*2 + 1];
            pa += fmaxf(lo - a[c], 0.f) + fmaxf(a[c] - hi, 0.f);
        }
    }
    atomicAdd(&s_coord, ca);
    atomicAdd(&s_p, pa);
    __syncthreads();
    if (t == 0) {
        float coord = s_coord / (float)(BATCH*NJ*3);
        float pl    = s_p / (float)(BATCH*NJ);
        float cham  = (g_cham1 + g_cham2) / (float)TOTAL;
        float jm = 0.f;
        for (int i = 0; i < NJ; i++) {
            float jl = (g_j1[i] + g_j2[i]) / (float)TOTAL;
            out[2 + i] = jl;
            jm += jl;
        }
        jm /= (float)NJ;
        out[0]  = 0.1f*cham + 0.1f*jm + coord + 0.1f*pl;
        out[1]  = coord;
        out[23] = cham;
        out[24] = pl;
    }
}

// ---------------- launch ----------------
extern "C" void kernel_launch(void* const* d_in, const int* in_sizes, int n_in,
                              void* d_out, int out_size) {
    const float* gen_pc      = (const float*)d_in[0];
    const int*   out_idxs    = (const int*)  d_in[1];
    const float* coords_pred = (const float*)d_in[2];
    const float* quats       = (const float*)d_in[3];
    const float* seg_logits  = (const float*)d_in[4];
    const float* bone_w      = (const float*)d_in[5];
    const float* tcoords     = (const float*)d_in[6];
    const float* target_pc   = (const float*)d_in[7];
    float* out = (float*)d_out;

    k_prep       <<<1, 1024>>>(bone_w);
    k_pack_label <<<TOTAL/256, 256>>>(gen_pc, out_idxs, seg_logits);
    k_sort       <<<BATCH, 512>>>(target_pc);
    k_main       <<<512, 128>>>(target_pc);
    k_final      <<<1, 256>>>(coords_pred, quats, tcoords, out);
}

// round 12
// speedup vs baseline: 1.2396x; 1.0972x over previous
#include <cuda_runtime.h>
#include <math.h>

#define BATCH 8
#define NPTS  2048
#define NJ    21
#define NWGT  778
#define TOTAL (BATCH*NPTS)

// ---------------- device scratch ----------------
__device__ unsigned int g_wbits[NWGT];
__device__ float4 g_q4[TOTAL];          // gen RAW: x,y,z,|q|^2
__device__ unsigned int g_qbits[TOTAL]; // gen joint-mask bits
__device__ int    g_label[TOTAL];       // argmin segment label per (b,m)
__device__ float4 g_tsorted[TOTAL];     // target sorted by label, SCALED: -2x,-2y,-2z,|t|^2
__device__ int    g_offs[BATCH*(NJ+1)];
__device__ float  g_cham1, g_cham2;
__device__ float  g_j1[NJ], g_j2[NJ];

__constant__ float c_ranges[NJ*6] = {
  -1.57f,1.57f, -1.57f,1.57f, -1.57f,1.57f,
  -1.05f,1.05f, 0.f,0.f, -0.79f,0.26f,
  -0.52f,0.52f, 0.f,0.f, -0.35f,0.79f,
  -0.26f,0.26f, 0.f,0.f, 0.f,0.f,
  -1.05f,0.f,   0.f,0.f, 0.f,0.f,
   0.f,0.f,     0.f,0.f, 0.f,0.f,
  -1.05f,0.26f, 0.f,0.f, -0.52f,0.26f,
  -0.52f,0.f,   0.f,0.f, 0.f,0.f,
  -0.52f,0.f,   0.f,0.f, 0.f,0.f,
   0.f,0.f,     0.f,0.f, 0.f,0.f,
  -1.05f,0.26f, 0.f,0.f, -0.52f,0.26f,
  -0.52f,0.f,   0.f,0.f, 0.f,0.f,
  -0.52f,0.f,   0.f,0.f, 0.f,0.f,
   0.f,0.f,     0.f,0.f, 0.f,0.f,
  -1.05f,0.26f, 0.f,0.f, -0.52f,0.26f,
  -0.52f,0.f,   0.f,0.f, 0.f,0.f,
  -0.52f,0.f,   0.f,0.f, 0.f,0.f,
   0.f,0.f,     0.f,0.f, 0.f,0.f,
  -1.05f,0.26f, 0.f,0.f, -0.52f,0.26f,
  -0.52f,0.f,   0.f,0.f, 0.f,0.f,
  -0.52f,0.f,   0.f,0.f, 0.f,0.f
};

// ---- K1: wbits + zero accumulators ----
__global__ void k_prep(const float* __restrict__ bw) {
    int t = threadIdx.x;
    if (t < NJ) { g_j1[t] = 0.f; g_j2[t] = 0.f; }
    if (t == 0) { g_cham1 = 0.f; g_cham2 = 0.f; }
    if (t < NWGT) {
        unsigned int bits = 0;
#pragma unroll
        for (int i = 0; i < NJ; i++)
            bits |= (bw[i*NWGT + t] > 0.15f) ? (1u << i) : 0u;
        g_wbits[t] = bits;
    }
}

// ---- K2: pack gen (norm + bits) + labels (coalesced via smem stage) ----
__global__ void __launch_bounds__(256) k_pack_label(
        const float* __restrict__ gen, const int* __restrict__ idxs,
        const float* __restrict__ seg) {
    __shared__ float sl[256*NJ];
    int t = threadIdx.x, blk = blockIdx.x;
    int gid = blk*256 + t;
    const float* segb = seg + (size_t)blk*256*NJ;
    for (int i = t; i < 256*NJ; i += 256) sl[i] = segb[i];
    float x = gen[3*gid], y = gen[3*gid+1], z = gen[3*gid+2];
    float4 q; q.x = x; q.y = y; q.z = z; q.w = x*x + y*y + z*z;
    g_q4[gid] = q;
    g_qbits[gid] = g_wbits[idxs[gid]];
    __syncthreads();
    const float* s = &sl[t*NJ];
    float best = s[0]; int bi = 0;
#pragma unroll
    for (int k = 1; k < NJ; k++) {
        float v = s[k];
        if (v < best) { best = v; bi = k; }
    }
    g_label[gid] = bi;
}

// ---- K3: per-batch counting sort; store pre-scaled (-2x,-2y,-2z,|t|^2) ----
__global__ void __launch_bounds__(512) k_sort(const float* __restrict__ tpc) {
    __shared__ int hist[NJ];
    __shared__ int cur[NJ];
    __shared__ int labs[NPTS];
    int t = threadIdx.x, b = blockIdx.x;
    if (t < NJ) hist[t] = 0;
    __syncthreads();
    int base = b << 11;
#pragma unroll
    for (int k = 0; k < 4; k++) {
        int i = t + 512*k;
        int lab = g_label[base + i];
        labs[i] = lab;
        atomicAdd(&hist[lab], 1);
    }
    __syncthreads();
    if (t == 0) {
        int run = 0;
        for (int j = 0; j < NJ; j++) {
            g_offs[b*(NJ+1) + j] = run;
            cur[j] = run;
            run += hist[j];
        }
        g_offs[b*(NJ+1) + NJ] = run;
    }
    __syncthreads();
#pragma unroll
    for (int k = 0; k < 4; k++) {
        int i = t + 512*k;
        int lab = labs[i];
        int pos = atomicAdd(&cur[lab], 1);
        int gi = base + i;
        float x = tpc[3*gi], y = tpc[3*gi+1], z = tpc[3*gi+2];
        float4 v;
        v.x = -2.f*x; v.y = -2.f*y; v.z = -2.f*z;
        v.w = x*x + y*y + z*z;
        g_tsorted[base + pos] = v;
    }
}

// ---- K4: FUSED main pass. Blocks [0,512): row; [512,1024): col.
// Per warp: 8 queries (2 per lane-group ql=lane&3), oct=lane>>2 splits range 8 ways.
struct RowS { float4 sT[NPTS]; int soff[NJ+1]; float sj[NJ]; float scham; };
struct ColS { float4 sQ[NPTS]; unsigned int sB[NPTS]; float sj[NJ]; float scham; };
union MainS { RowS r; ColS c; };

__global__ void __launch_bounds__(128) k_main(const float* __restrict__ tpc) {
    __shared__ MainS sm;
    int t = threadIdx.x;
    int warp = t >> 5, lane = t & 31;
    int oct = lane >> 2, ql = lane & 3;

    if (blockIdx.x < 512) {
        // ================= ROW =================
        int b = blockIdx.x >> 6;            // 64 blocks per batch
        int qblk = blockIdx.x & 63;         // 32 queries per block
        for (int i = t; i < NPTS; i += 128) sm.r.sT[i] = g_tsorted[(b << 11) + i];
        if (t < NJ+1) sm.r.soff[t] = g_offs[b*(NJ+1) + t];
        if (t < NJ) sm.r.sj[t] = 0.f;
        if (t == 0) sm.r.scham = 0.f;
        __syncthreads();

        int qbase = (b << 11) + qblk*32 + warp*8;
        float4 qa = g_q4[qbase + ql];
        float4 qb = g_q4[qbase + 4 + ql];
        unsigned int bits_a = g_qbits[qbase + ql];
        unsigned int bits_b = g_qbits[qbase + 4 + ql];
        float gmall_a = 1e30f, gmall_b = 1e30f;

        for (int grp = 0; grp < NJ; grp++) {
            int s = sm.r.soff[grp], e = sm.r.soff[grp+1];
            int hlen = (e - s + 7) >> 3;
            int m0 = s + oct*hlen;
            int mend = min(m0 + hlen, e);
            float gma = 1e30f, gmb = 1e30f;
#pragma unroll 4
            for (int m = m0; m < mend; m++) {
                float4 tp = sm.r.sT[m];                   // pre-scaled -2
                float va = fmaf(qa.x, tp.x, tp.w);
                va = fmaf(qa.y, tp.y, va);
                va = fmaf(qa.z, tp.z, va);
                float vb = fmaf(qb.x, tp.x, tp.w);
                vb = fmaf(qb.y, tp.y, vb);
                vb = fmaf(qb.z, tp.z, vb);
                gma = fminf(gma, va);
                gmb = fminf(gmb, vb);
            }
            gma = fminf(gma, __shfl_xor_sync(0xffffffffu, gma, 4));
            gma = fminf(gma, __shfl_xor_sync(0xffffffffu, gma, 8));
            gma = fminf(gma, __shfl_xor_sync(0xffffffffu, gma, 16));
            gmb = fminf(gmb, __shfl_xor_sync(0xffffffffu, gmb, 4));
            gmb = fminf(gmb, __shfl_xor_sync(0xffffffffu, gmb, 8));
            gmb = fminf(gmb, __shfl_xor_sync(0xffffffffu, gmb, 16));
            gmall_a = fminf(gmall_a, gma);
            gmall_b = fminf(gmall_b, gmb);
            if (oct == 0 && ((bits_a >> grp) & 1u)) {
                float d = sqrtf(fmaxf(gma + qa.w, 0.f));
                if (d < 10.f) atomicAdd(&sm.r.sj[grp], d);
            }
            if (oct == 1 && ((bits_b >> grp) & 1u)) {
                float d = sqrtf(fmaxf(gmb + qb.w, 0.f));
                if (d < 10.f) atomicAdd(&sm.r.sj[grp], d);
            }
        }
        if (oct == 0) atomicAdd(&sm.r.scham, sqrtf(fmaxf(gmall_a + qa.w, 0.f)));
        if (oct == 1) atomicAdd(&sm.r.scham, sqrtf(fmaxf(gmall_b + qb.w, 0.f)));
        __syncthreads();
        if (t < NJ) atomicAdd(&g_j1[t], sm.r.sj[t]);
        if (t == 0) atomicAdd(&g_cham1, sm.r.scham);
    } else {
        // ================= COL =================
        int blk = blockIdx.x - 512;
        int b = blk >> 6;
        int mblk = blk & 63;
        for (int i = t; i < NPTS; i += 128) {
            float4 v = g_q4[(b << 11) + i];
            v.x *= -2.f; v.y *= -2.f; v.z *= -2.f;    // scale into tile
            sm.c.sQ[i] = v;
            sm.c.sB[i] = g_qbits[(b << 11) + i];
        }
        if (t < NJ) sm.c.sj[t] = 0.f;
        if (t == 0) sm.c.scham = 0.f;
        __syncthreads();

        int mbase = (b << 11) + mblk*32 + warp*8;
        int gia = mbase + ql, gib = mbase + 4 + ql;
        float tax = tpc[3*gia], tay = tpc[3*gia+1], taz = tpc[3*gia+2];
        float tbx = tpc[3*gib], tby = tpc[3*gib+1], tbz = tpc[3*gib+2];
        float tan2 = tax*tax + tay*tay + taz*taz;
        float tbn2 = tbx*tbx + tby*tby + tbz*tbz;
        int pa = g_label[gia], pb = g_label[gib];
        unsigned int maska = 1u << pa, maskb = 1u << pb;
        float gmina = 1e30f, gminb = 1e30f, pmina = 1e30f, pminb = 1e30f;
        int n0 = oct * (NPTS/8);

#pragma unroll 4
        for (int i = 0; i < NPTS/8; i++) {
            int n = n0 + i;
            float4 qn = sm.c.sQ[n];                       // pre-scaled -2
            unsigned int bb = sm.c.sB[n];
            float va = fmaf(tax, qn.x, qn.w);
            va = fmaf(tay, qn.y, va);
            va = fmaf(taz, qn.z, va);
            float vb = fmaf(tbx, qn.x, qn.w);
            vb = fmaf(tby, qn.y, vb);
            vb = fmaf(tbz, qn.z, vb);
            gmina = fminf(gmina, va);
            gminb = fminf(gminb, vb);
            pmina = fminf(pmina, (bb & maska) ? va : 1e30f);
            pminb = fminf(pminb, (bb & maskb) ? vb : 1e30f);
        }
#pragma unroll
        for (int o = 4; o <= 16; o <<= 1) {
            gmina = fminf(gmina, __shfl_xor_sync(0xffffffffu, gmina, o));
            gminb = fminf(gminb, __shfl_xor_sync(0xffffffffu, gminb, o));
            pmina = fminf(pmina, __shfl_xor_sync(0xffffffffu, pmina, o));
            pminb = fminf(pminb, __shfl_xor_sync(0xffffffffu, pminb, o));
        }
        if (oct == 0) {
            atomicAdd(&sm.c.scham, sqrtf(fmaxf(gmina + tan2, 0.f)));
            float dj = sqrtf(fmaxf(pmina + tan2, 0.f));
            if (dj < 10.f) atomicAdd(&sm.c.sj[pa], dj);
        }
        if (oct == 1) {
            atomicAdd(&sm.c.scham, sqrtf(fmaxf(gminb + tbn2, 0.f)));
            float dj = sqrtf(fmaxf(pminb + tbn2, 0.f));
            if (dj < 10.f) atomicAdd(&sm.c.sj[pb], dj);
        }
        __syncthreads();
        if (t < NJ) atomicAdd(&g_j2[t], sm.c.sj[t]);
        if (t == 0) atomicAdd(&g_cham2, sm.c.scham);
    }
}

// ---- K5: finalize ----
__global__ void k_final(const float* __restrict__ cp, const float* __restrict__ qt,
                        const float* __restrict__ tc, float* __restrict__ out) {
    __shared__ float s_coord, s_p;
    int t = threadIdx.x;
    if (t == 0) { s_coord = 0.f; s_p = 0.f; }
    __syncthreads();

    float ca = 0.f;
    for (int i = t; i < BATCH*NJ*3; i += blockDim.x) {
        float d = cp[i] - tc[i];
        ca += d * d;
    }
    float pa = 0.f;
    for (int i = t; i < BATCH*NJ; i += blockDim.x) {
        int j = i % NJ;
        float w = qt[4*i], x = qt[4*i+1], y = qt[4*i+2], z = qt[4*i+3];
        float inv = 1.0f / sqrtf(w*w + x*x + y*y + z*z);
        w *= inv; x *= inv; y *= inv; z *= inv;
        float a0 = atan2f(2.f*(w*x + y*z), 1.f - 2.f*(x*x + y*y));
        float a1 = asinf(fminf(fmaxf(2.f*(w*y - z*x), -1.f), 1.f));
        float a2 = atan2f(2.f*(w*z + x*y), 1.f - 2.f*(y*y + z*z));
        float a[3] = {a0, a1, a2};
#pragma unroll
        for (int c = 0; c < 3; c++) {
            float lo = c_ranges[j*6 + c*2], hi = c_ranges[j*6 + c*2 + 1];
            pa += fmaxf(lo - a[c], 0.f) + fmaxf(a[c] - hi, 0.f);
        }
    }
    atomicAdd(&s_coord, ca);
    atomicAdd(&s_p, pa);
    __syncthreads();
    if (t == 0) {
        float coord = s_coord / (float)(BATCH*NJ*3);
        float pl    = s_p / (float)(BATCH*NJ);
        float cham  = (g_cham1 + g_cham2) / (float)TOTAL;
        float jm = 0.f;
        for (int i = 0; i < NJ; i++) {
            float jl = (g_j1[i] + g_j2[i]) / (float)TOTAL;
            out[2 + i] = jl;
            jm += jl;
        }
        jm /= (float)NJ;
        out[0]  = 0.1f*cham + 0.1f*jm + coord + 0.1f*pl;
        out[1]  = coord;
        out[23] = cham;
        out[24] = pl;
    }
}

// ---------------- launch ----------------
extern "C" void kernel_launch(void* const* d_in, const int* in_sizes, int n_in,
                              void* d_out, int out_size) {
    const float* gen_pc      = (const float*)d_in[0];
    const int*   out_idxs    = (const int*)  d_in[1];
    const float* coords_pred = (const float*)d_in[2];
    const float* quats       = (const float*)d_in[3];
    const float* seg_logits  = (const float*)d_in[4];
    const float* bone_w      = (const float*)d_in[5];
    const float* tcoords     = (const float*)d_in[6];
    const float* target_pc   = (const float*)d_in[7];
    float* out = (float*)d_out;

    k_prep       <<<1, 1024>>>(bone_w);
    k_pack_label <<<TOTAL/256, 256>>>(gen_pc, out_idxs, seg_logits);
    k_sort       <<<BATCH, 512>>>(target_pc);
    k_main       <<<1024, 128>>>(target_pc);
    k_final      <<<1, 256>>>(coords_pred, quats, tcoords, out);
}